// round 6
// baseline (speedup 1.0000x reference)
#include <cuda_runtime.h>

#define BATCH 128
#define SITES 256
#define BOND 64
#define NOUT 10
#define HALFS 128          // sites per half
#define TILE_BYTES 32768   // 64*64*2 floats per site
#define STAGES 6

typedef unsigned long long ull;

// Scratch (device globals — no allocation allowed)
// Both halves repacked: [t][h][jj][olocal] float4 = (c0[2jj][o], c1[2jj][o], c0[2jj+1][o], c1[2jj+1][o])
__device__ __align__(16) float g_L[HALFS * 8192];
__device__ __align__(16) float g_R[HALFS * 8192];
__device__ float g_vL[BATCH * BOND];
__device__ float g_wR[BATCH * BOND];

// ---- packed f32x2 helpers ----
static __device__ __forceinline__ ull ffma2(ull a, ull b, ull c) {
    ull d;
    asm("fma.rn.f32x2 %0, %1, %2, %3;" : "=l"(d) : "l"(a), "l"(b), "l"(c));
    return d;
}
static __device__ __forceinline__ ull fadd2(ull a, ull b) {
    ull d;
    asm("add.rn.f32x2 %0, %1, %2;" : "=l"(d) : "l"(a), "l"(b));
    return d;
}
static __device__ __forceinline__ float f2lo(ull v) {
    return __uint_as_float((unsigned)(v & 0xffffffffull));
}
static __device__ __forceinline__ float f2hi(ull v) {
    return __uint_as_float((unsigned)(v >> 32));
}
static __device__ __forceinline__ ull dup2(float v) {
    unsigned u = __float_as_uint(v);
    return ((ull)u << 32) | u;
}
static __device__ __forceinline__ unsigned smem_u32(const void* p) {
    return (unsigned)__cvta_generic_to_shared(p);
}

// ---- mbarrier / bulk-copy primitives ----
static __device__ __forceinline__ void mbar_init(unsigned addr, unsigned count) {
    asm volatile("mbarrier.init.shared.b64 [%0], %1;" :: "r"(addr), "r"(count) : "memory");
}
static __device__ __forceinline__ void mbar_expect_tx(unsigned addr, unsigned bytes) {
    asm volatile("mbarrier.arrive.expect_tx.shared.b64 _, [%0], %1;"
                 :: "r"(addr), "r"(bytes) : "memory");
}
static __device__ __forceinline__ void mbar_wait(unsigned addr, unsigned parity) {
    asm volatile(
        "{\n\t"
        ".reg .pred P;\n\t"
        "WAIT_%=:\n\t"
        "mbarrier.try_wait.parity.acquire.cta.shared::cta.b64 P, [%0], %1, 0x989680;\n\t"
        "@P bra.uni DONE_%=;\n\t"
        "bra.uni WAIT_%=;\n\t"
        "DONE_%=:\n\t"
        "}"
        :: "r"(addr), "r"(parity) : "memory");
}
static __device__ __forceinline__ void bulk_g2s(unsigned dst, const void* src,
                                                unsigned bytes, unsigned mbar) {
    asm volatile(
        "cp.async.bulk.shared::cluster.global.mbarrier::complete_tx::bytes [%0], [%1], %2, [%3];"
        :: "r"(dst), "l"(src), "r"(bytes), "r"(mbar) : "memory");
}

// ============================================================
// Kernel 1: repack both halves into the chain-friendly layout.
// Output float4 index m (0..2047) per tile: m = (o>>5)*1024 + jj*32 + (o&31)
//   left  (t = s):       out = (c0[l=2jj][r=o], c1[2jj][o], c0[2jj+1][o], c1[2jj+1][o])
//   right (t = 255 - s): out = (c0[l=o][r=2jj], c1[o][2jj], c0[o][2jj+1], c1[o][2jj+1])
// ============================================================
__global__ void __launch_bounds__(256) repack_kernel(const float* __restrict__ cores) {
    const int right = blockIdx.x >> 7;          // 0 = left, 1 = right
    const int t = blockIdx.x & 127;
    const int s = right ? (255 - t) : t;
    const float* src = cores + (size_t)s * 8192;

    __shared__ __align__(16) char shraw[64 * 66 * 8];  // 33792 B

    if (!right) {
        // stage transposed: sh2[o*66 + l] = srcF2[l*64 + o]
        float2* sh2 = (float2*)shraw;
        const float2* s2 = (const float2*)src;
        for (int idx = threadIdx.x; idx < 4096; idx += 256) {
            int l = idx >> 6, o = idx & 63;
            sh2[o * 66 + l] = s2[idx];
        }
        __syncthreads();
        float4* dst = (float4*)g_L + (size_t)t * 2048;
        for (int m = threadIdx.x; m < 2048; m += 256) {
            int o = ((m >> 10) << 5) | (m & 31);
            int jj = (m >> 5) & 31;
            float2 a = sh2[o * 66 + 2 * jj];
            float2 b = sh2[o * 66 + 2 * jj + 1];
            dst[m] = make_float4(a.x, a.y, b.x, b.y);
        }
    } else {
        // stage identity: sh4[o*33 + jj] = srcF4[o*32 + jj]
        float4* sh4 = (float4*)shraw;
        const float4* s4 = (const float4*)src;
        for (int m = threadIdx.x; m < 2048; m += 256) {
            int o = m >> 5, jj = m & 31;
            sh4[o * 33 + jj] = s4[m];
        }
        __syncthreads();
        float4* dst = (float4*)g_R + (size_t)t * 2048;
        for (int m = threadIdx.x; m < 2048; m += 256) {
            int o = ((m >> 10) << 5) | (m & 31);
            int jj = (m >> 5) & 31;
            dst[m] = sh4[o * 33 + jj];
        }
    }
}

// ============================================================
// Kernel 2: vector chains.
// grid (32, 2): 32 batch-groups (4 batches) x 2 halves. 128 threads = 4 warps.
// warp w: h = w & 1 (output half), p = w >> 1 (chain pair).
// Lane owns one output o = 32h + lane for both chains of its pair.
// Tiles stream through a 6-deep cp.async.bulk ring; state double-buffered
// so one __syncthreads per site covers write-visibility + stage reuse.
// ============================================================
__global__ void __launch_bounds__(128) chain_kernel(
    const float* __restrict__ x,      // [B][S][2]
    const float* __restrict__ lvec,
    const float* __restrict__ rvec)
{
    extern __shared__ __align__(128) char dynsmem[];   // STAGES * 32KB
    __shared__ __align__(16) ull st[2][4][64];         // [buf][chain][j] = (v,v)
    __shared__ __align__(16) float2 sx[4][HALFS];      // per-chain x, site order
    __shared__ __align__(8) ull mbar_store[STAGES];

    const int tid  = threadIdx.x;
    const int w    = tid >> 5;
    const int lane = tid & 31;
    const int h    = w & 1;
    const int p    = w >> 1;
    const int half = blockIdx.y;
    const int o    = h * 32 + lane;
    const int cA   = 2 * p, cB = 2 * p + 1;

    unsigned mb[STAGES];
    #pragma unroll
    for (int si = 0; si < STAGES; ++si) mb[si] = smem_u32(&mbar_store[si]);
    if (tid == 0) {
        #pragma unroll
        for (int si = 0; si < STAGES; ++si) mbar_init(mb[si], 1);
    }

    // Stage per-chain x values (site order t).
    for (int i = tid; i < 4 * HALFS; i += 128) {
        int c = i >> 7, t = i & 127;
        int batch = blockIdx.x * 4 + c;
        int s = half ? (255 - t) : t;
        sx[c][t] = *(const float2*)(x + ((size_t)batch * SITES + s) * 2);
    }
    // Init state buffer 0 with the boundary vector.
    const float* bv = half ? rvec : lvec;
    for (int i = tid; i < 4 * 64; i += 128) {
        int c = i >> 6, j = i & 63;
        st[0][c][j] = dup2(bv[j]);
    }
    __syncthreads();

    const char* gsrc = half ? (const char*)g_R : (const char*)g_L;

    if (tid == 0) {
        #pragma unroll
        for (int si = 0; si < STAGES; ++si) {
            mbar_expect_tx(mb[si], TILE_BYTES);
            bulk_g2s(smem_u32(dynsmem + (size_t)si * TILE_BYTES),
                     gsrc + (size_t)si * TILE_BYTES, TILE_BYTES, mb[si]);
        }
    }

    for (int t = 0; t < HALFS; ++t) {
        const int stg = t % STAGES;
        const int cur = t & 1;
        mbar_wait(mb[stg], (t / STAGES) & 1);

        // half-tile view: 1024 16B units per output-half
        const ulonglong2* tp =
            (const ulonglong2*)(dynsmem + (size_t)stg * TILE_BYTES) + h * 1024 + lane;
        const ulonglong2* sA = (const ulonglong2*)&st[cur][cA][0];
        const ulonglong2* sB = (const ulonglong2*)&st[cur][cB][0];

        ull a0 = 0, a1 = 0, b0 = 0, b1 = 0;
        #pragma unroll
        for (int jj = 0; jj < 32; ++jj) {
            ulonglong2 c  = tp[jj * 32];   // ((c0,c1)@j=2jj , (c0,c1)@j=2jj+1) for output o
            ulonglong2 vA = sA[jj];        // ((v,v)@2jj , (v,v)@2jj+1) chain A  (broadcast)
            ulonglong2 vB = sB[jj];
            a0 = ffma2(c.x, vA.x, a0);
            a1 = ffma2(c.y, vA.y, a1);
            b0 = ffma2(c.x, vB.x, b0);
            b1 = ffma2(c.y, vB.y, b1);
        }
        ull dA = fadd2(a0, a1);   // (dot_f0, dot_f1) for chain A, output o
        ull dB = fadd2(b0, b1);

        const float2 xA = sx[cA][t];
        const float2 xB = sx[cB][t];
        const float oldA = f2lo(st[cur][cA][o]);
        const float oldB = f2lo(st[cur][cB][o]);
        const float nA = fmaf(xA.x, f2lo(dA), fmaf(xA.y, f2hi(dA), oldA));
        const float nB = fmaf(xB.x, f2lo(dB), fmaf(xB.y, f2hi(dB), oldB));

        st[cur ^ 1][cA][o] = dup2(nA);
        st[cur ^ 1][cB][o] = dup2(nB);

        __syncthreads();  // state visible; all warps done reading stage stg

        if (tid == 0 && t + STAGES < HALFS) {
            mbar_expect_tx(mb[stg], TILE_BYTES);
            bulk_g2s(smem_u32(dynsmem + (size_t)stg * TILE_BYTES),
                     gsrc + (size_t)(t + STAGES) * TILE_BYTES, TILE_BYTES, mb[stg]);
        }
    }

    // Final state lives in buffer (127&1)^1 = 0.
    float* dst = half ? g_wR : g_vL;
    const int bA = blockIdx.x * 4 + cA;
    const int bB = blockIdx.x * 4 + cB;
    dst[bA * 64 + o] = f2lo(st[0][cA][o]);
    dst[bB * 64 + o] = f2lo(st[0][cB][o]);
}

// ============================================================
// Kernel 3: logits[b][o] = sum_{l,r} vL[l] * oc[o][l][r] * wR[r]
// ============================================================
__global__ void __launch_bounds__(64) combine_kernel(
    const float* __restrict__ oc, float* __restrict__ out)
{
    const int b = blockIdx.x;
    const int tid = threadIdx.x; // 0..63 = r
    __shared__ float vL[64], wR[64];
    __shared__ float red[2];
    vL[tid] = g_vL[b * 64 + tid];
    wR[tid] = g_wR[b * 64 + tid];
    __syncthreads();
    const float w = wR[tid];
    for (int o = 0; o < NOUT; ++o) {
        float acc = 0.f;
        const float* row = oc + (size_t)o * 4096 + tid;
        #pragma unroll 16
        for (int l = 0; l < 64; ++l)
            acc = fmaf(vL[l], row[(size_t)l * 64], acc);
        float pv = acc * w;
        #pragma unroll
        for (int off = 16; off; off >>= 1)
            pv += __shfl_down_sync(0xffffffffu, pv, off);
        if ((tid & 31) == 0) red[tid >> 5] = pv;
        __syncthreads();
        if (tid == 0) out[b * NOUT + o] = red[0] + red[1];
        __syncthreads();
    }
}

extern "C" void kernel_launch(void* const* d_in, const int* in_sizes, int n_in,
                              void* d_out, int out_size) {
    const float* input_data = (const float*)d_in[0]; // [128,256,2]
    const float* cores      = (const float*)d_in[1]; // [256,64,64,2]
    const float* out_core   = (const float*)d_in[2]; // [10,64,64]
    const float* lvec       = (const float*)d_in[3]; // [64]
    const float* rvec       = (const float*)d_in[4]; // [64]
    float* out = (float*)d_out;                      // [128,10]

    cudaFuncSetAttribute(chain_kernel,
                         cudaFuncAttributeMaxDynamicSharedMemorySize,
                         STAGES * TILE_BYTES);

    repack_kernel<<<2 * HALFS, 256>>>(cores);
    chain_kernel<<<dim3(32, 2), 128, STAGES * TILE_BYTES>>>(input_data, lvec, rvec);
    combine_kernel<<<BATCH, 64>>>(out_core, out);
}

// round 7
// speedup vs baseline: 2.1224x; 2.1224x over previous
#include <cuda_runtime.h>

#define BATCH 128
#define SITES 256
#define BOND 64
#define NOUT 10
#define HALFS 128            // sites per half
#define SITE_BYTES 32768     // 64*64*2 floats
#define PAIR_BYTES 65536     // 2 sites per TMA stage
#define STAGES 3             // 3 * 64KB = 192KB ring

typedef unsigned long long ull;

// Scratch (device globals — no allocation allowed)
__device__ __align__(16) float g_ct[HALFS * BOND * BOND * 2]; // right half, transposed+reversed
__device__ float g_vL[BATCH * BOND];
__device__ float g_wR[BATCH * BOND];

// ---- packed f32x2 helpers ----
static __device__ __forceinline__ ull ffma2(ull a, ull b, ull c) {
    ull d;
    asm("fma.rn.f32x2 %0, %1, %2, %3;" : "=l"(d) : "l"(a), "l"(b), "l"(c));
    return d;
}
static __device__ __forceinline__ ull fadd2(ull a, ull b) {
    ull d;
    asm("add.rn.f32x2 %0, %1, %2;" : "=l"(d) : "l"(a), "l"(b));
    return d;
}
static __device__ __forceinline__ float f2lo(ull v) {
    return __uint_as_float((unsigned)(v & 0xffffffffull));
}
static __device__ __forceinline__ float f2hi(ull v) {
    return __uint_as_float((unsigned)(v >> 32));
}
static __device__ __forceinline__ ull dup2(float v) {
    unsigned u = __float_as_uint(v);
    return ((ull)u << 32) | u;
}
static __device__ __forceinline__ unsigned smem_u32(const void* p) {
    return (unsigned)__cvta_generic_to_shared(p);
}

// ---- mbarrier / bulk-copy primitives ----
static __device__ __forceinline__ void mbar_init(unsigned addr, unsigned count) {
    asm volatile("mbarrier.init.shared.b64 [%0], %1;" :: "r"(addr), "r"(count) : "memory");
}
static __device__ __forceinline__ void mbar_expect_tx(unsigned addr, unsigned bytes) {
    asm volatile("mbarrier.arrive.expect_tx.shared.b64 _, [%0], %1;"
                 :: "r"(addr), "r"(bytes) : "memory");
}
static __device__ __forceinline__ void mbar_wait(unsigned addr, unsigned parity) {
    asm volatile(
        "{\n\t"
        ".reg .pred P;\n\t"
        "WAIT_%=:\n\t"
        "mbarrier.try_wait.parity.acquire.cta.shared::cta.b64 P, [%0], %1, 0x989680;\n\t"
        "@P bra.uni DONE_%=;\n\t"
        "bra.uni WAIT_%=;\n\t"
        "DONE_%=:\n\t"
        "}"
        :: "r"(addr), "r"(parity) : "memory");
}
static __device__ __forceinline__ void bulk_g2s(unsigned dst, const void* src,
                                                unsigned bytes, unsigned mbar) {
    asm volatile(
        "cp.async.bulk.shared::cluster.global.mbarrier::complete_tx::bytes [%0], [%1], %2, [%3];"
        :: "r"(dst), "l"(src), "r"(bytes), "r"(mbar) : "memory");
}

// ============================================================
// Kernel 1: repack right-half cores only.
// g_ct[t][r][2l+i] = cores[255 - t][l][r][i]  (transpose, reverse order)
// ============================================================
__global__ void __launch_bounds__(256) repack_kernel(const float* __restrict__ cores) {
    int t = blockIdx.x;            // 0..127
    int s = 255 - t;
    __shared__ float2 sh[64 * 65];
    const float2* src = (const float2*)cores + (size_t)s * 4096; // [l*64 + r] -> (c0,c1)
    float2* dst = (float2*)g_ct + (size_t)t * 4096;              // [r*64 + l]
    for (int idx = threadIdx.x; idx < 4096; idx += blockDim.x) {
        int l = idx >> 6, r = idx & 63;
        sh[r * 65 + l] = src[idx];
    }
    __syncthreads();
    for (int idx = threadIdx.x; idx < 4096; idx += blockDim.x) {
        int r = idx >> 6, l = idx & 63;
        dst[idx] = sh[r * 65 + l];
    }
}

// ============================================================
// Kernel 2: vector chains. ONE warp per block, 2 chains per warp,
// lane owns outputs o0 = 2*lane, o0+1 for both chains.
// grid (64, 2) = 128 blocks. No __syncthreads anywhere in the loop;
// state is double-buffered so exactly one __syncwarp per site.
// Tiles stream via a 3-deep x 2-site cp.async.bulk ring (64KB stages),
// so one mbar_wait per 2 sites.
// ============================================================
__global__ void __launch_bounds__(32) chain_kernel(
    const float* __restrict__ x,      // [B][S][2]
    const float* __restrict__ cores,  // [S][l][r][2]
    const float* __restrict__ lvec,
    const float* __restrict__ rvec)
{
    extern __shared__ __align__(128) char dynsmem[];   // STAGES * 64KB
    __shared__ __align__(16) ull st[2][2][64];         // [buf][chain][j] = (v,v)
    __shared__ __align__(16) float2 sx[2][HALFS];      // per-chain x, site order
    __shared__ __align__(8) ull mbar_store[STAGES];

    const int lane = threadIdx.x;
    const int half = blockIdx.y;
    const int o0   = 2 * lane;

    unsigned mb[STAGES];
    #pragma unroll
    for (int si = 0; si < STAGES; ++si) mb[si] = smem_u32(&mbar_store[si]);
    if (lane == 0) {
        #pragma unroll
        for (int si = 0; si < STAGES; ++si) mbar_init(mb[si], 1);
    }

    // Stage per-chain x values (site order t).
    for (int i = lane; i < 2 * HALFS; i += 32) {
        int c = i >> 7, t = i & 127;
        int batch = blockIdx.x * 2 + c;
        int s = half ? (255 - t) : t;
        sx[c][t] = *(const float2*)(x + ((size_t)batch * SITES + s) * 2);
    }
    // Init state buffer 0 with the boundary vector.
    const float* bv = half ? rvec : lvec;
    {
        float v0 = bv[o0], v1 = bv[o0 + 1];
        st[0][0][o0] = dup2(v0); st[0][0][o0 + 1] = dup2(v1);
        st[0][1][o0] = dup2(v0); st[0][1][o0 + 1] = dup2(v1);
    }
    __syncwarp();

    const char* gsrc = half ? (const char*)g_ct : (const char*)cores;

    // Prime: 3 stage-pairs (sites 0..5).
    if (lane == 0) {
        #pragma unroll
        for (int pr = 0; pr < STAGES; ++pr) {
            mbar_expect_tx(mb[pr], PAIR_BYTES);
            bulk_g2s(smem_u32(dynsmem + (size_t)pr * PAIR_BYTES),
                     gsrc + (size_t)pr * PAIR_BYTES, PAIR_BYTES, mb[pr]);
        }
    }

    for (int t = 0; t < HALFS; ++t) {
        const int pair = t >> 1;
        const int stg  = pair % STAGES;
        if ((t & 1) == 0)
            mbar_wait(mb[stg], (pair / STAGES) & 1);

        const int cur = t & 1;  // state read buffer; write buffer = cur^1
        const ulonglong2* tp =
            (const ulonglong2*)(dynsmem + (size_t)stg * PAIR_BYTES + (size_t)cur * SITE_BYTES)
            + lane;
        const ulonglong2* sA = (const ulonglong2*)&st[cur][0][0];
        const ulonglong2* sB = (const ulonglong2*)&st[cur][1][0];

        ull a0 = 0, a1 = 0, a2 = 0, a3 = 0;   // chain A: o0 even-rows, o0+1 even, o0 odd, o0+1 odd
        ull b0 = 0, b1 = 0, b2 = 0, b3 = 0;   // chain B
        #pragma unroll
        for (int jj = 0; jj < 32; ++jj) {
            ulonglong2 ca = tp[(2 * jj) * 32];       // row 2jj:  (c0,c1) for o0 | o0+1
            ulonglong2 cb = tp[(2 * jj + 1) * 32];   // row 2jj+1
            ulonglong2 vA = sA[jj];                  // (v,v)@2jj | (v,v)@2jj+1 (broadcast)
            ulonglong2 vB = sB[jj];
            a0 = ffma2(ca.x, vA.x, a0);
            a1 = ffma2(ca.y, vA.x, a1);
            a2 = ffma2(cb.x, vA.y, a2);
            a3 = ffma2(cb.y, vA.y, a3);
            b0 = ffma2(ca.x, vB.x, b0);
            b1 = ffma2(ca.y, vB.x, b1);
            b2 = ffma2(cb.x, vB.y, b2);
            b3 = ffma2(cb.y, vB.y, b3);
        }
        ull dA0 = fadd2(a0, a2);   // (dot_f0, dot_f1) chain A, output o0
        ull dA1 = fadd2(a1, a3);   // output o0+1
        ull dB0 = fadd2(b0, b2);
        ull dB1 = fadd2(b1, b3);

        const float2 xA = sx[0][t];
        const float2 xB = sx[1][t];
        const float oA0 = f2lo(st[cur][0][o0]);
        const float oA1 = f2lo(st[cur][0][o0 + 1]);
        const float oB0 = f2lo(st[cur][1][o0]);
        const float oB1 = f2lo(st[cur][1][o0 + 1]);
        const float nA0 = fmaf(xA.x, f2lo(dA0), fmaf(xA.y, f2hi(dA0), oA0));
        const float nA1 = fmaf(xA.x, f2lo(dA1), fmaf(xA.y, f2hi(dA1), oA1));
        const float nB0 = fmaf(xB.x, f2lo(dB0), fmaf(xB.y, f2hi(dB0), oB0));
        const float nB1 = fmaf(xB.x, f2lo(dB1), fmaf(xB.y, f2hi(dB1), oB1));

        // write next-site state (other buffer); one syncwarp makes it visible
        // and guarantees all lanes finished reading buffer `cur^1`'s previous
        // contents before it gets overwritten next site.
        ulonglong2* wA = (ulonglong2*)&st[cur ^ 1][0][o0];
        ulonglong2* wB = (ulonglong2*)&st[cur ^ 1][1][o0];
        *wA = make_ulonglong2(dup2(nA0), dup2(nA1));
        *wB = make_ulonglong2(dup2(nB0), dup2(nB1));
        __syncwarp();

        // After finishing a pair (odd t), refill its stage for pair+3.
        if ((t & 1) == 1 && lane == 0 && pair + STAGES < HALFS / 2) {
            mbar_expect_tx(mb[stg], PAIR_BYTES);
            bulk_g2s(smem_u32(dynsmem + (size_t)stg * PAIR_BYTES),
                     gsrc + (size_t)(pair + STAGES) * PAIR_BYTES, PAIR_BYTES, mb[stg]);
        }
    }

    // 128 sites -> final state in buffer 0.
    float* dst = half ? g_wR : g_vL;
    const int bA = blockIdx.x * 2;
    dst[bA * 64 + o0]           = f2lo(st[0][0][o0]);
    dst[bA * 64 + o0 + 1]       = f2lo(st[0][0][o0 + 1]);
    dst[(bA + 1) * 64 + o0]     = f2lo(st[0][1][o0]);
    dst[(bA + 1) * 64 + o0 + 1] = f2lo(st[0][1][o0 + 1]);
}

// ============================================================
// Kernel 3: logits[b][o] = sum_{l,r} vL[l] * oc[o][l][r] * wR[r]
// ============================================================
__global__ void __launch_bounds__(64) combine_kernel(
    const float* __restrict__ oc, float* __restrict__ out)
{
    const int b = blockIdx.x;
    const int tid = threadIdx.x; // 0..63 = r
    __shared__ float vL[64], wR[64];
    __shared__ float red[2];
    vL[tid] = g_vL[b * 64 + tid];
    wR[tid] = g_wR[b * 64 + tid];
    __syncthreads();
    const float w = wR[tid];
    for (int o = 0; o < NOUT; ++o) {
        float acc = 0.f;
        const float* row = oc + (size_t)o * 4096 + tid;
        #pragma unroll 16
        for (int l = 0; l < 64; ++l)
            acc = fmaf(vL[l], row[(size_t)l * 64], acc);
        float pv = acc * w;
        #pragma unroll
        for (int off = 16; off; off >>= 1)
            pv += __shfl_down_sync(0xffffffffu, pv, off);
        if ((tid & 31) == 0) red[tid >> 5] = pv;
        __syncthreads();
        if (tid == 0) out[b * NOUT + o] = red[0] + red[1];
        __syncthreads();
    }
}

extern "C" void kernel_launch(void* const* d_in, const int* in_sizes, int n_in,
                              void* d_out, int out_size) {
    const float* input_data = (const float*)d_in[0]; // [128,256,2]
    const float* cores      = (const float*)d_in[1]; // [256,64,64,2]
    const float* out_core   = (const float*)d_in[2]; // [10,64,64]
    const float* lvec       = (const float*)d_in[3]; // [64]
    const float* rvec       = (const float*)d_in[4]; // [64]
    float* out = (float*)d_out;                      // [128,10]

    cudaFuncSetAttribute(chain_kernel,
                         cudaFuncAttributeMaxDynamicSharedMemorySize,
                         STAGES * PAIR_BYTES);

    repack_kernel<<<HALFS, 256>>>(cores);
    chain_kernel<<<dim3(64, 2), 32, STAGES * PAIR_BYTES>>>(input_data, cores, lvec, rvec);
    combine_kernel<<<BATCH, 64>>>(out_core, out);
}